// round 15
// baseline (speedup 1.0000x reference)
#include <cuda_runtime.h>
#include <cuda_fp16.h>
#include <cuda_bf16.h>
#include <cstdint>
#include <cstddef>

#define TLEN   2048
#define NBATCH 2
#define DMODEL 1024
#define DSTATE 64
#define DCONV  4
#define DINNER 2048
#define DPROJ  4288
#define DTRANK 64
#define MROWS  (NBATCH * TLEN)   // 4096

// ---------------- scratch (static device globals; no allocation) ----------------
__device__ float g_proj [(size_t)MROWS * DPROJ];   // 70.3 MB
__device__ float g_delta[(size_t)MROWS * DINNER];  // 33.6 MB

// fp16 operand buffers (16B aligned for cp.async / vector loads)
__device__ __align__(16) __half g_xh [(size_t)MROWS * DMODEL];
__device__ __align__(16) __half g_w1h[(size_t)DPROJ * DMODEL];
__device__ __align__(16) __half g_w2h[(size_t)DMODEL * DINNER];
__device__ __align__(16) __half g_yh [(size_t)MROWS * DINNER];

// ---------------- small math helpers ----------------
__device__ __forceinline__ float ex2f(float x) {
    float y;
    asm("ex2.approx.f32 %0, %1;" : "=f"(y) : "f"(x));
    return y;
}
__device__ __forceinline__ float sigmoidf_(float x) {
    return 1.0f / (1.0f + __expf(-x));
}
__device__ __forceinline__ float softplusf_(float x) {
    return (x > 20.0f) ? x : log1pf(__expf(x));
}

// ---------------- sm_80-level async/MMA primitives (legal under compute_103) ----------------
__device__ __forceinline__ uint32_t smem_to_u32(const void* p) {
    uint32_t a;
    asm("{ .reg .u64 t; cvta.to.shared.u64 t, %1; cvt.u32.u64 %0, t; }" : "=r"(a) : "l"(p));
    return a;
}
__device__ __forceinline__ void ldsm4(uint32_t* r, uint32_t addr) {
    asm volatile("ldmatrix.sync.aligned.m8n8.x4.shared.b16 {%0,%1,%2,%3}, [%4];"
                 : "=r"(r[0]), "=r"(r[1]), "=r"(r[2]), "=r"(r[3]) : "r"(addr));
}
__device__ __forceinline__ void mma16816h(float* d, const uint32_t* a, const uint32_t* b) {
    asm volatile(
        "mma.sync.aligned.m16n8k16.row.col.f32.f16.f16.f32 "
        "{%0,%1,%2,%3}, {%4,%5,%6,%7}, {%8,%9}, {%0,%1,%2,%3};"
        : "+f"(d[0]), "+f"(d[1]), "+f"(d[2]), "+f"(d[3])
        : "r"(a[0]), "r"(a[1]), "r"(a[2]), "r"(a[3]), "r"(b[0]), "r"(b[1]));
}
__device__ __forceinline__ void cpa16(uint32_t saddr, const void* g) {
    asm volatile("cp.async.cg.shared.global [%0], [%1], 16;" :: "r"(saddr), "l"(g));
}
__device__ __forceinline__ void cpa_commit() {
    asm volatile("cp.async.commit_group;" ::: "memory");
}
template<int N_>
__device__ __forceinline__ void cpa_wait() {
    asm volatile("cp.async.wait_group %0;" :: "n"(N_) : "memory");
}

// ---------------- fp32 -> fp16 convert ----------------
__global__ __launch_bounds__(256)
void cvt_fp16_kernel(const float* __restrict__ src, __half* __restrict__ dst, int n4)
{
    int i = blockIdx.x * blockDim.x + threadIdx.x;
    if (i >= n4) return;
    float4 v = ((const float4*)src)[i];
    __half h[4];
    h[0] = __float2half(v.x); h[1] = __float2half(v.y);
    h[2] = __float2half(v.z); h[3] = __float2half(v.w);
    *(uint2*)(dst + 4 * (size_t)i) = *(uint2*)h;
}

// ---------------- HMMA fp16 GEMM: C[M,N] = A[M,K] @ B[N,K]^T ----------------
// CTA 128x128, 8 warps (warp tile m32 x n64), BK=64, 3-stage cp.async pipeline.
#define ROWB   144
#define TILEB  (128 * ROWB)      // 18432
#define STAGEB (2 * TILEB)       // 36864
#define NSTG   3
#define SMEMB  (NSTG * STAGEB)   // 110592

__global__ void __launch_bounds__(256, 2)
gemm_mma_fp16(const __half* __restrict__ A, const __half* __restrict__ B,
              float* __restrict__ C, int M, int N, int K)
{
    extern __shared__ __align__(128) char smem[];
    const uint32_t sb = smem_to_u32(smem);

    const int tid  = threadIdx.x;
    const int wid  = tid >> 5;
    const int lane = tid & 31;
    const int m0 = blockIdx.y * 128;
    const int n0 = blockIdx.x * 128;
    const int wm = (wid & 3) * 32;
    const int wn = (wid >> 2) * 64;

    const int NC = K >> 6;

    float acc[2][8][4];
#pragma unroll
    for (int a = 0; a < 2; a++)
#pragma unroll
        for (int b = 0; b < 8; b++)
#pragma unroll
            for (int c = 0; c < 4; c++) acc[a][b][c] = 0.0f;

    auto bufof = [](int cidx) { return cidx - (cidx / NSTG) * NSTG; };

    auto load_stage = [&](int cidx) {
        const int k0 = cidx << 6;
        uint32_t base = sb + bufof(cidx) * STAGEB;
#pragma unroll
        for (int it = 0; it < 8; it++) {
            int idx = it * 256 + tid;
            int row = (idx >> 3) & 127;
            int c16 = idx & 7;
            uint32_t soff = (uint32_t)(row * ROWB + c16 * 16);
            if (idx < 1024) {
                size_t gA = (size_t)(m0 + row) * K + k0 + c16 * 8;
                cpa16(base + soff, A + gA);
            } else {
                int gn = n0 + row;
                if (gn >= N) gn = N - 1;
                size_t gB = (size_t)gn * K + k0 + c16 * 8;
                cpa16(base + TILEB + soff, B + gB);
            }
        }
    };

    load_stage(0); cpa_commit();
    if (NC > 1) load_stage(1);
    cpa_commit();

    for (int cidx = 0; cidx < NC; cidx++) {
        cpa_wait<1>();
        __syncthreads();

        if (cidx + 2 < NC) load_stage(cidx + 2);
        cpa_commit();

        const uint32_t base = sb + bufof(cidx) * STAGEB;
        const uint32_t aB = base;
        const uint32_t bB = base + TILEB;

#pragma unroll
        for (int ks = 0; ks < 4; ks++) {
            uint32_t ah[2][4];
            {
                int rr = ((lane >> 3) & 1) * 8 + (lane & 7);
                int cc = ks * 16 + (lane >> 4) * 8;
#pragma unroll
                for (int mf = 0; mf < 2; mf++) {
                    uint32_t off = (uint32_t)((wm + mf * 16 + rr) * ROWB + cc * 2);
                    ldsm4(ah[mf], aB + off);
                }
            }
            {
                int rr = ((lane >> 4) & 1) * 8 + (lane & 7);
                int cc = ks * 16 + ((lane >> 3) & 1) * 8;
#pragma unroll
                for (int ng = 0; ng < 4; ng++) {
                    uint32_t bh[4];
                    uint32_t off = (uint32_t)((wn + ng * 16 + rr) * ROWB + cc * 2);
                    ldsm4(bh, bB + off);
#pragma unroll
                    for (int mf = 0; mf < 2; mf++) {
                        mma16816h(acc[mf][ng * 2 + 0], ah[mf], &bh[0]);
                        mma16816h(acc[mf][ng * 2 + 1], ah[mf], &bh[2]);
                    }
                }
            }
        }
    }

#pragma unroll
    for (int mf = 0; mf < 2; mf++)
#pragma unroll
        for (int nf = 0; nf < 8; nf++) {
            int rr = m0 + wm + mf * 16 + (lane >> 2);
            int cc = n0 + wn + nf * 8 + (lane & 3) * 2;
            if (cc < N) {
                *(float2*)(C + (size_t)rr * N + cc) =
                    make_float2(acc[mf][nf][0], acc[mf][nf][1]);
                *(float2*)(C + (size_t)(rr + 8) * N + cc) =
                    make_float2(acc[mf][nf][2], acc[mf][nf][3]);
            }
        }
}

// ---------------- SIMT NT GEMM (dt_proj, K=64) ----------------
template<int EPI>
__global__ __launch_bounds__(256)
void gemm_nt(const float* __restrict__ A, int lda,
             const float* __restrict__ B, int ldb,
             float* __restrict__ C, int ldc,
             int M, int N, int K,
             const float* __restrict__ bias)
{
    constexpr int BM = 128, BN = 128, BK = 16;
    __shared__ float As[BK][BM];
    __shared__ float Bs[BK][BN];

    const int tid = threadIdx.x;
    const int tx = tid & 15;
    const int ty = tid >> 4;
    const int m0 = blockIdx.y * BM;
    const int n0 = blockIdx.x * BN;
    const int lrow = tid >> 2;
    const int lcol = (tid & 3) << 2;

    float acc[8][8];
#pragma unroll
    for (int i = 0; i < 8; i++)
#pragma unroll
        for (int j = 0; j < 8; j++) acc[i][j] = 0.0f;

    for (int k0 = 0; k0 < K; k0 += BK) {
#pragma unroll
        for (int r = 0; r < 2; r++) {
            int row = lrow + r * 64;
            int gm = m0 + row;
            float4 v = make_float4(0.f, 0.f, 0.f, 0.f);
            if (gm < M) v = *(const float4*)(A + (size_t)gm * lda + k0 + lcol);
            As[lcol + 0][row] = v.x; As[lcol + 1][row] = v.y;
            As[lcol + 2][row] = v.z; As[lcol + 3][row] = v.w;
        }
#pragma unroll
        for (int r = 0; r < 2; r++) {
            int row = lrow + r * 64;
            int gn = n0 + row;
            float4 v = make_float4(0.f, 0.f, 0.f, 0.f);
            if (gn < N) v = *(const float4*)(B + (size_t)gn * ldb + k0 + lcol);
            Bs[lcol + 0][row] = v.x; Bs[lcol + 1][row] = v.y;
            Bs[lcol + 2][row] = v.z; Bs[lcol + 3][row] = v.w;
        }
        __syncthreads();
#pragma unroll
        for (int kk = 0; kk < BK; kk++) {
            float a[8], b[8];
            *(float4*)(a)     = *(const float4*)&As[kk][ty * 8];
            *(float4*)(a + 4) = *(const float4*)&As[kk][ty * 8 + 4];
            *(float4*)(b)     = *(const float4*)&Bs[kk][tx * 8];
            *(float4*)(b + 4) = *(const float4*)&Bs[kk][tx * 8 + 4];
#pragma unroll
            for (int i = 0; i < 8; i++)
#pragma unroll
                for (int j = 0; j < 8; j++)
                    acc[i][j] = fmaf(a[i], b[j], acc[i][j]);
        }
        __syncthreads();
    }

#pragma unroll
    for (int ii = 0; ii < 8; ii++) {
        int gm = m0 + ty * 8 + ii;
        if (gm >= M) continue;
#pragma unroll
        for (int jj = 0; jj < 8; jj += 4) {
            int gn = n0 + tx * 8 + jj;
            if (gn >= N) continue;
            float4 v;
            if (EPI == 0) {
                v = make_float4(acc[ii][jj], acc[ii][jj + 1], acc[ii][jj + 2], acc[ii][jj + 3]);
            } else {
                v.x = softplusf_(acc[ii][jj]     + bias[gn]);
                v.y = softplusf_(acc[ii][jj + 1] + bias[gn + 1]);
                v.z = softplusf_(acc[ii][jj + 2] + bias[gn + 2]);
                v.w = softplusf_(acc[ii][jj + 3] + bias[gn + 3]);
            }
            *(float4*)(C + (size_t)gm * ldc + gn) = v;
        }
    }
}

// ---------------- selective scan v6: 2 channels/lane, 32 channels/block ----------------
// Block = 256 threads (8 warps), 32 channels; warp = 4 channels (2 per lane).
// 128 blocks (single wave, 1 CTA/SM). B/C float4 reads amortized over 4 channels/warp.
// Partials stored as float2 {p_c0, p_c1} in P2[t][chpair][sub] -> conflict-free STS.64.
#define SW   32    // timesteps per chunk
#define SCH  32    // channels per block
#define SNCH (TLEN / SW)   // 64 chunks

struct ScanSmem {
    float  BC[2][SW][128];       // B (64) then C (64) per timestep    32 KB
    float  D [2][SW][SCH];       // delta                               8 KB
    float  Z [2][SW][SCH];       // z                                   8 KB
    float  XI[2][SW + 4][SCH];   // x_inner rows t0-3 .. t0+32          9 KB
    float  XC[2][SW][SCH];       // conv+silu output                    8 KB
    float2 P2[SW][SCH / 2][16];  // paired partials                    64 KB
    float  Dsm[SCH];
    float  CW[SCH][4];
    float  CB[SCH];
};                                // ~130 KB

__global__ void __launch_bounds__(256, 1)
scan_kernel6(const float* __restrict__ proj,
             const float* __restrict__ delta,
             const float* __restrict__ A_log,
             const float* __restrict__ D_param,
             const float* __restrict__ conv_w,
             const float* __restrict__ conv_b,
             __half* __restrict__ yh,
             float* __restrict__ hT)
{
    extern __shared__ __align__(16) char smraw[];
    ScanSmem* sm = (ScanSmem*)smraw;

    const int tid  = threadIdx.x;
    const int warp = tid >> 5;                   // 0..7
    const int lane = tid & 31;
    const int b    = blockIdx.x >> 6;            // 64 blocks per batch
    const int i0   = (blockIdx.x & 63) * SCH;
    const int pr   = lane >> 4;                  // half-warp pair index 0/1
    const int c0   = (warp << 2) + (pr << 1);    // first channel of lane's pair [0,32)
    const int sub  = lane & 15;
    const int s0   = sub << 2;                   // states [s0, s0+4)
    const int cpair = c0 >> 1;                   // [0,16)

    float A2[4];
#pragma unroll
    for (int j = 0; j < 4; j++)
        A2[j] = -__expf(A_log[s0 + j]) * 1.4426950408889634f;  // A * log2(e)

    // stage per-channel constants
    if (tid < 32) {
        sm->Dsm[tid] = D_param[i0 + tid];
        sm->CB[tid]  = conv_b[i0 + tid];
    } else if (tid < 160) {
        int t2 = tid - 32;
        sm->CW[t2 >> 2][t2 & 3] = conv_w[(i0 + (t2 >> 2)) * DCONV + (t2 & 3)];
    }

    float ha0 = 0.f, ha1 = 0.f, ha2 = 0.f, ha3 = 0.f;   // channel c0
    float hb0 = 0.f, hb1 = 0.f, hb2 = 0.f, hb3 = 0.f;   // channel c0+1

    auto fill = [&](int buf, int c) {
        const int t0 = c * SW;
        const float* basebc = proj + ((size_t)(b * TLEN + t0)) * DPROJ + 2 * DINNER;
        // BC: 32 rows x 512B = 1024 x 16B chunks, 4 per thread
#pragma unroll
        for (int it = 0; it < 4; it++) {
            int idx = it * 256 + tid;
            int r = idx >> 5, cc = idx & 31;
            cpa16(smem_to_u32(&sm->BC[buf][r][cc * 4]), basebc + (size_t)r * DPROJ + cc * 4);
        }
        // D and Z: 32 rows x 128B = 256 chunks each, 1 per thread
        {
            int r = tid >> 3, cc = (tid & 7) * 4;
            size_t rowi = (size_t)(b * TLEN + t0 + r);
            cpa16(smem_to_u32(&sm->D[buf][r][cc]), delta + rowi * DINNER + i0 + cc);
            cpa16(smem_to_u32(&sm->Z[buf][r][cc]), proj + rowi * DPROJ + DINNER + i0 + cc);
        }
        // XI: 36 rows x 32 ch = 288 x 16B chunks
#pragma unroll
        for (int it = 0; it < 2; it++) {
            int idx = it * 256 + tid;
            if (idx < 288) {
                int rr = idx >> 3, cc = (idx & 7) * 4;
                int gt = t0 - 3 + rr;
                if (gt >= 0 && gt < TLEN) {
                    cpa16(smem_to_u32(&sm->XI[buf][rr][cc]),
                          proj + ((size_t)(b * TLEN + gt)) * DPROJ + i0 + cc);
                } else {
                    *(float4*)&sm->XI[buf][rr][cc] = make_float4(0.f, 0.f, 0.f, 0.f);
                }
            }
        }
    };

    fill(0, 0); cpa_commit();
    fill(1, 1); cpa_commit();

    for (int c = 0; c < SNCH; c++) {
        const int buf = c & 1;
        cpa_wait<1>();
        __syncthreads();                        // chunk c inputs ready; P2 free

        // conv + bias + silu: 32t x 32ch = 1024 vals, 4 per thread
        {
            int t = tid >> 3, ch0 = (tid & 7) * 4;
#pragma unroll
            for (int v = 0; v < 4; v++) {
                int ch = ch0 + v;
                float a = sm->CB[ch];
#pragma unroll
                for (int k = 0; k < DCONV; k++)
                    a = fmaf(sm->XI[buf][t + k][ch], sm->CW[ch][k], a);
                sm->XC[buf][t][ch] = a * sigmoidf_(a);
            }
        }
        __syncthreads();                        // XC visible

        // recurrence: 2 channels/lane, broadcast B/C, one STS.64 per step
#pragma unroll 4
        for (int t = 0; t < SW; t++) {
            float2 dv = *(const float2*)&sm->D[buf][t][c0];
            float2 xv = *(const float2*)&sm->XC[buf][t][c0];
            float dua = dv.x * xv.x;
            float dub = dv.y * xv.y;
            float4 Bv = *(const float4*)&sm->BC[buf][t][s0];
            float4 Cv = *(const float4*)&sm->BC[buf][t][64 + s0];

            ha0 = fmaf(ex2f(A2[0] * dv.x), ha0, dua * Bv.x);
            ha1 = fmaf(ex2f(A2[1] * dv.x), ha1, dua * Bv.y);
            ha2 = fmaf(ex2f(A2[2] * dv.x), ha2, dua * Bv.z);
            ha3 = fmaf(ex2f(A2[3] * dv.x), ha3, dua * Bv.w);
            hb0 = fmaf(ex2f(A2[0] * dv.y), hb0, dub * Bv.x);
            hb1 = fmaf(ex2f(A2[1] * dv.y), hb1, dub * Bv.y);
            hb2 = fmaf(ex2f(A2[2] * dv.y), hb2, dub * Bv.z);
            hb3 = fmaf(ex2f(A2[3] * dv.y), hb3, dub * Bv.w);

            float pa = fmaf(ha0, Cv.x, fmaf(ha1, Cv.y, fmaf(ha2, Cv.z, ha3 * Cv.w)));
            float pb = fmaf(hb0, Cv.x, fmaf(hb1, Cv.y, fmaf(hb2, Cv.z, hb3 * Cv.w)));
            sm->P2[t][cpair][sub] = make_float2(pa, pb);
        }
        __syncthreads();                        // P2 complete

        // flush: 32t x 32ch outputs, 4 channels (2 cpairs) per thread
        {
            const int t0 = c * SW;
            int t = tid >> 3, ch0 = (tid & 7) * 4;
            __half hv[4];
#pragma unroll
            for (int cp = 0; cp < 2; cp++) {
                const float4* p = (const float4*)&sm->P2[t][(ch0 >> 1) + cp][0];
                float sa = 0.f, sb2 = 0.f;
#pragma unroll
                for (int j = 0; j < 8; j++) {
                    float4 v4 = p[j];
                    sa  += v4.x + v4.z;
                    sb2 += v4.y + v4.w;
                }
                int cA = ch0 + cp * 2, cB = cA + 1;
                sa  = fmaf(sm->Dsm[cA], sm->XC[buf][t][cA], sa);
                sb2 = fmaf(sm->Dsm[cB], sm->XC[buf][t][cB], sb2);
                float zA = sm->Z[buf][t][cA], zB = sm->Z[buf][t][cB];
                sa  *= zA * sigmoidf_(zA);
                sb2 *= zB * sigmoidf_(zB);
                hv[cp * 2 + 0] = __float2half(sa);
                hv[cp * 2 + 1] = __float2half(sb2);
            }
            *(uint2*)(yh + ((size_t)(b * TLEN + t0 + t)) * DINNER + i0 + ch0) =
                *(uint2*)hv;
        }
        __syncthreads();                        // flush reads done; buf free

        if (c + 2 < SNCH) fill(buf, c + 2);
        cpa_commit();
    }

    // final hidden state: two channels x 4 states per lane
    float* hpA = hT + ((size_t)(b * DINNER + i0 + c0)) * DSTATE + s0;
    float* hpB = hT + ((size_t)(b * DINNER + i0 + c0 + 1)) * DSTATE + s0;
    *(float4*)hpA = make_float4(ha0, ha1, ha2, ha3);
    *(float4*)hpB = make_float4(hb0, hb1, hb2, hb3);
}

// ---------------- launch ----------------
extern "C" void kernel_launch(void* const* d_in, const int* in_sizes, int n_in,
                              void* d_out, int out_size)
{
    const float* x       = (const float*)d_in[0];   // [2,2048,1024]
    const float* in_proj = (const float*)d_in[1];   // [4288,1024]
    const float* conv_w  = (const float*)d_in[2];   // [2048,1,4]
    const float* conv_b  = (const float*)d_in[3];   // [2048]
    const float* A_log   = (const float*)d_in[4];   // [64]
    const float* D_param = (const float*)d_in[5];   // [2048]
    const float* dt_w    = (const float*)d_in[6];   // [2048,64]
    const float* dt_b    = (const float*)d_in[7];   // [2048]
    const float* out_w   = (const float*)d_in[8];   // [1024,2048]
    float* out = (float*)d_out;                     // out (4194304) then hT (262144)

    float *pproj, *pdelta;
    cudaGetSymbolAddress((void**)&pproj,  g_proj);
    cudaGetSymbolAddress((void**)&pdelta, g_delta);

    __half *xh, *w1h, *w2h, *yh;
    cudaGetSymbolAddress((void**)&xh,  g_xh);
    cudaGetSymbolAddress((void**)&w1h, g_w1h);
    cudaGetSymbolAddress((void**)&w2h, g_w2h);
    cudaGetSymbolAddress((void**)&yh,  g_yh);

    cudaFuncSetAttribute(gemm_mma_fp16,
                         cudaFuncAttributeMaxDynamicSharedMemorySize, SMEMB);
    cudaFuncSetAttribute(scan_kernel6,
                         cudaFuncAttributeMaxDynamicSharedMemorySize, (int)sizeof(ScanSmem));

    // convert inputs to fp16
    {
        int n4 = (MROWS * DMODEL) / 4;
        cvt_fp16_kernel<<<(n4 + 255) / 256, 256>>>(x, xh, n4);
        n4 = (DPROJ * DMODEL) / 4;
        cvt_fp16_kernel<<<(n4 + 255) / 256, 256>>>(in_proj, w1h, n4);
        n4 = (DMODEL * DINNER) / 4;
        cvt_fp16_kernel<<<(n4 + 255) / 256, 256>>>(out_w, w2h, n4);
    }

    // 1) proj = x @ in_proj_w^T   [4096 x 4288]  (HMMA fp16, BK=64)
    gemm_mma_fp16<<<dim3((DPROJ + 127) / 128, MROWS / 128), 256, SMEMB>>>(
        xh, w1h, pproj, MROWS, DPROJ, DMODEL);

    // 2) delta = softplus(delta_raw @ dt_proj_w^T + dt_proj_b)  [4096 x 2048] K=64 (SIMT)
    gemm_nt<1><<<dim3(DINNER / 128, MROWS / 128), 256>>>(
        pproj + 2 * DINNER + 2 * DSTATE, DPROJ, dt_w, DTRANK, pdelta, DINNER,
        MROWS, DINNER, DTRANK, dt_b);

    // 3) selective scan v6 (2 ch/lane, conv fused); writes yh fp16 + hT tail of d_out
    scan_kernel6<<<128, 256, sizeof(ScanSmem)>>>(pproj, pdelta, A_log, D_param,
                                                 conv_w, conv_b,
                                                 yh, out + (size_t)MROWS * DMODEL);

    // 4) out = y @ out_proj_w^T   [4096 x 1024]  (HMMA fp16, BK=64)
    gemm_mma_fp16<<<dim3(DMODEL / 128, MROWS / 128), 256, SMEMB>>>(
        yh, w2h, out, MROWS, DMODEL, DINNER);
}

// round 16
// speedup vs baseline: 1.0618x; 1.0618x over previous
#include <cuda_runtime.h>
#include <cuda_fp16.h>
#include <cuda_bf16.h>
#include <cstdint>
#include <cstddef>

#define TLEN   2048
#define NBATCH 2
#define DMODEL 1024
#define DSTATE 64
#define DCONV  4
#define DINNER 2048
#define DPROJ  4288
#define DTRANK 64
#define MROWS  (NBATCH * TLEN)   // 4096

// ---------------- scratch (static device globals; no allocation) ----------------
__device__ float g_proj [(size_t)MROWS * DPROJ];   // 70.3 MB
__device__ float g_delta[(size_t)MROWS * DINNER];  // 33.6 MB

// fp16 operand buffers (16B aligned for cp.async / vector loads)
__device__ __align__(16) __half g_xh [(size_t)MROWS * DMODEL];
__device__ __align__(16) __half g_w1h[(size_t)DPROJ * DMODEL];
__device__ __align__(16) __half g_w2h[(size_t)DMODEL * DINNER];
__device__ __align__(16) __half g_yh [(size_t)MROWS * DINNER];

// ---------------- small math helpers ----------------
__device__ __forceinline__ float ex2f(float x) {
    float y;
    asm("ex2.approx.f32 %0, %1;" : "=f"(y) : "f"(x));
    return y;
}
__device__ __forceinline__ float sigmoidf_(float x) {
    return 1.0f / (1.0f + __expf(-x));
}
__device__ __forceinline__ float softplusf_(float x) {
    return (x > 20.0f) ? x : log1pf(__expf(x));
}

// ---------------- sm_80-level async/MMA primitives (legal under compute_103) ----------------
__device__ __forceinline__ uint32_t smem_to_u32(const void* p) {
    uint32_t a;
    asm("{ .reg .u64 t; cvta.to.shared.u64 t, %1; cvt.u32.u64 %0, t; }" : "=r"(a) : "l"(p));
    return a;
}
__device__ __forceinline__ void ldsm4(uint32_t* r, uint32_t addr) {
    asm volatile("ldmatrix.sync.aligned.m8n8.x4.shared.b16 {%0,%1,%2,%3}, [%4];"
                 : "=r"(r[0]), "=r"(r[1]), "=r"(r[2]), "=r"(r[3]) : "r"(addr));
}
__device__ __forceinline__ void mma16816h(float* d, const uint32_t* a, const uint32_t* b) {
    asm volatile(
        "mma.sync.aligned.m16n8k16.row.col.f32.f16.f16.f32 "
        "{%0,%1,%2,%3}, {%4,%5,%6,%7}, {%8,%9}, {%0,%1,%2,%3};"
        : "+f"(d[0]), "+f"(d[1]), "+f"(d[2]), "+f"(d[3])
        : "r"(a[0]), "r"(a[1]), "r"(a[2]), "r"(a[3]), "r"(b[0]), "r"(b[1]));
}
__device__ __forceinline__ void cpa16(uint32_t saddr, const void* g) {
    asm volatile("cp.async.cg.shared.global [%0], [%1], 16;" :: "r"(saddr), "l"(g));
}
__device__ __forceinline__ void cpa_commit() {
    asm volatile("cp.async.commit_group;" ::: "memory");
}
template<int N_>
__device__ __forceinline__ void cpa_wait() {
    asm volatile("cp.async.wait_group %0;" :: "n"(N_) : "memory");
}

// ---------------- fp32 -> fp16 convert ----------------
__global__ __launch_bounds__(256)
void cvt_fp16_kernel(const float* __restrict__ src, __half* __restrict__ dst, int n4)
{
    int i = blockIdx.x * blockDim.x + threadIdx.x;
    if (i >= n4) return;
    float4 v = ((const float4*)src)[i];
    __half h[4];
    h[0] = __float2half(v.x); h[1] = __float2half(v.y);
    h[2] = __float2half(v.z); h[3] = __float2half(v.w);
    *(uint2*)(dst + 4 * (size_t)i) = *(uint2*)h;
}

// ---------------- HMMA fp16 GEMM: C[M,N] = A[M,K] @ B[N,K]^T ----------------
// CTA 128x128, 8 warps (warp tile m32 x n64), BK=64, 3-stage cp.async pipeline,
// ONE __syncthreads per chunk. Row pitch 144B (128B data + 16B pad) -> conflict-free.
#define ROWB   144
#define TILEB  (128 * ROWB)      // 18432
#define STAGEB (2 * TILEB)       // 36864
#define NSTG   3
#define SMEMB  (NSTG * STAGEB)   // 110592

__global__ void __launch_bounds__(256, 2)
gemm_mma_fp16(const __half* __restrict__ A, const __half* __restrict__ B,
              float* __restrict__ C, int M, int N, int K)
{
    extern __shared__ __align__(128) char smem[];
    const uint32_t sb = smem_to_u32(smem);

    const int tid  = threadIdx.x;
    const int wid  = tid >> 5;
    const int lane = tid & 31;
    const int m0 = blockIdx.y * 128;
    const int n0 = blockIdx.x * 128;
    const int wm = (wid & 3) * 32;
    const int wn = (wid >> 2) * 64;

    const int NC = K >> 6;           // 64-wide k chunks

    float acc[2][8][4];
#pragma unroll
    for (int a = 0; a < 2; a++)
#pragma unroll
        for (int b = 0; b < 8; b++)
#pragma unroll
            for (int c = 0; c < 4; c++) acc[a][b][c] = 0.0f;

    auto bufof = [](int cidx) { return cidx - (cidx / NSTG) * NSTG; };

    auto load_stage = [&](int cidx) {
        const int k0 = cidx << 6;
        uint32_t base = sb + bufof(cidx) * STAGEB;
#pragma unroll
        for (int it = 0; it < 8; it++) {
            int idx = it * 256 + tid;          // 0..2047
            int row = (idx >> 3) & 127;
            int c16 = idx & 7;
            uint32_t soff = (uint32_t)(row * ROWB + c16 * 16);
            if (idx < 1024) {
                size_t gA = (size_t)(m0 + row) * K + k0 + c16 * 8;
                cpa16(base + soff, A + gA);
            } else {
                int gn = n0 + row;
                if (gn >= N) gn = N - 1;
                size_t gB = (size_t)gn * K + k0 + c16 * 8;
                cpa16(base + TILEB + soff, B + gB);
            }
        }
    };

    load_stage(0); cpa_commit();
    if (NC > 1) load_stage(1);
    cpa_commit();

    for (int cidx = 0; cidx < NC; cidx++) {
        cpa_wait<1>();
        __syncthreads();                 // stage cidx ready; buf (cidx+2)%3 free

        if (cidx + 2 < NC) load_stage(cidx + 2);
        cpa_commit();

        const uint32_t base = sb + bufof(cidx) * STAGEB;
        const uint32_t aB = base;
        const uint32_t bB = base + TILEB;

#pragma unroll
        for (int ks = 0; ks < 4; ks++) {
            uint32_t ah[2][4];
            {
                int rr = ((lane >> 3) & 1) * 8 + (lane & 7);
                int cc = ks * 16 + (lane >> 4) * 8;
#pragma unroll
                for (int mf = 0; mf < 2; mf++) {
                    uint32_t off = (uint32_t)((wm + mf * 16 + rr) * ROWB + cc * 2);
                    ldsm4(ah[mf], aB + off);
                }
            }
            {
                int rr = ((lane >> 4) & 1) * 8 + (lane & 7);
                int cc = ks * 16 + ((lane >> 3) & 1) * 8;
#pragma unroll
                for (int ng = 0; ng < 4; ng++) {
                    uint32_t bh[4];
                    uint32_t off = (uint32_t)((wn + ng * 16 + rr) * ROWB + cc * 2);
                    ldsm4(bh, bB + off);
#pragma unroll
                    for (int mf = 0; mf < 2; mf++) {
                        mma16816h(acc[mf][ng * 2 + 0], ah[mf], &bh[0]);
                        mma16816h(acc[mf][ng * 2 + 1], ah[mf], &bh[2]);
                    }
                }
            }
        }
    }

    // epilogue: registers -> global (float2 stores)
#pragma unroll
    for (int mf = 0; mf < 2; mf++)
#pragma unroll
        for (int nf = 0; nf < 8; nf++) {
            int rr = m0 + wm + mf * 16 + (lane >> 2);
            int cc = n0 + wn + nf * 8 + (lane & 3) * 2;
            if (cc < N) {
                *(float2*)(C + (size_t)rr * N + cc) =
                    make_float2(acc[mf][nf][0], acc[mf][nf][1]);
                *(float2*)(C + (size_t)(rr + 8) * N + cc) =
                    make_float2(acc[mf][nf][2], acc[mf][nf][3]);
            }
        }
}

// ---------------- SIMT NT GEMM (dt_proj, K=64) ----------------
template<int EPI>
__global__ __launch_bounds__(256)
void gemm_nt(const float* __restrict__ A, int lda,
             const float* __restrict__ B, int ldb,
             float* __restrict__ C, int ldc,
             int M, int N, int K,
             const float* __restrict__ bias)
{
    constexpr int BM = 128, BN = 128, BK = 16;
    __shared__ float As[BK][BM];
    __shared__ float Bs[BK][BN];

    const int tid = threadIdx.x;
    const int tx = tid & 15;
    const int ty = tid >> 4;
    const int m0 = blockIdx.y * BM;
    const int n0 = blockIdx.x * BN;
    const int lrow = tid >> 2;
    const int lcol = (tid & 3) << 2;

    float acc[8][8];
#pragma unroll
    for (int i = 0; i < 8; i++)
#pragma unroll
        for (int j = 0; j < 8; j++) acc[i][j] = 0.0f;

    for (int k0 = 0; k0 < K; k0 += BK) {
#pragma unroll
        for (int r = 0; r < 2; r++) {
            int row = lrow + r * 64;
            int gm = m0 + row;
            float4 v = make_float4(0.f, 0.f, 0.f, 0.f);
            if (gm < M) v = *(const float4*)(A + (size_t)gm * lda + k0 + lcol);
            As[lcol + 0][row] = v.x; As[lcol + 1][row] = v.y;
            As[lcol + 2][row] = v.z; As[lcol + 3][row] = v.w;
        }
#pragma unroll
        for (int r = 0; r < 2; r++) {
            int row = lrow + r * 64;
            int gn = n0 + row;
            float4 v = make_float4(0.f, 0.f, 0.f, 0.f);
            if (gn < N) v = *(const float4*)(B + (size_t)gn * ldb + k0 + lcol);
            Bs[lcol + 0][row] = v.x; Bs[lcol + 1][row] = v.y;
            Bs[lcol + 2][row] = v.z; Bs[lcol + 3][row] = v.w;
        }
        __syncthreads();
#pragma unroll
        for (int kk = 0; kk < BK; kk++) {
            float a[8], b[8];
            *(float4*)(a)     = *(const float4*)&As[kk][ty * 8];
            *(float4*)(a + 4) = *(const float4*)&As[kk][ty * 8 + 4];
            *(float4*)(b)     = *(const float4*)&Bs[kk][tx * 8];
            *(float4*)(b + 4) = *(const float4*)&Bs[kk][tx * 8 + 4];
#pragma unroll
            for (int i = 0; i < 8; i++)
#pragma unroll
                for (int j = 0; j < 8; j++)
                    acc[i][j] = fmaf(a[i], b[j], acc[i][j]);
        }
        __syncthreads();
    }

#pragma unroll
    for (int ii = 0; ii < 8; ii++) {
        int gm = m0 + ty * 8 + ii;
        if (gm >= M) continue;
#pragma unroll
        for (int jj = 0; jj < 8; jj += 4) {
            int gn = n0 + tx * 8 + jj;
            if (gn >= N) continue;
            float4 v;
            if (EPI == 0) {
                v = make_float4(acc[ii][jj], acc[ii][jj + 1], acc[ii][jj + 2], acc[ii][jj + 3]);
            } else {
                v.x = softplusf_(acc[ii][jj]     + bias[gn]);
                v.y = softplusf_(acc[ii][jj + 1] + bias[gn + 1]);
                v.z = softplusf_(acc[ii][jj + 2] + bias[gn + 2]);
                v.w = softplusf_(acc[ii][jj + 3] + bias[gn + 3]);
            }
            *(float4*)(C + (size_t)gm * ldc + gn) = v;
        }
    }
}

// ---------------- selective scan v4b: fused conv+silu, packed (delta, delta*xc) ----------------
// Proven v4 config (256 thr, 16 ch, 2 CTAs/SM) + DU2 float2 pack: recurrence loop
// does one LDS.64 instead of two scalar LDS and starts with du ready.
#define SW   32    // timesteps per chunk
#define SCH  16    // channels per block
#define SNCH (TLEN / SW)   // 64 chunks

struct ScanSmem {
    float  BC[2][SW][128];      // B (64) then C (64) per timestep     32 KB
    float  D [2][SW][SCH];      // delta (cp.async landing)             4 KB
    float  Z [2][SW][SCH];      // z                                    4 KB
    float  XI[2][SW + 4][SCH];  // x_inner rows t0-3 .. t0+32          4.5 KB
    float  XC[2][SW][SCH];      // conv+silu output                     4 KB
    float2 DU2[2][SW][SCH];     // packed (delta, delta*xc)             8 KB
    float  P [SW][SCH][16];     // per-lane partial h.C                32 KB
    float  Dsm[SCH];
    float  CW[SCH][4];
    float  CB[SCH];
};                               // ~89 KB (2 CTAs/SM fits 178 KB <= 228)

__global__ void __launch_bounds__(256, 2)
scan_kernel4(const float* __restrict__ proj,
             const float* __restrict__ delta,
             const float* __restrict__ A_log,
             const float* __restrict__ D_param,
             const float* __restrict__ conv_w,
             const float* __restrict__ conv_b,
             __half* __restrict__ yh,
             float* __restrict__ hT)
{
    extern __shared__ __align__(16) char smraw[];
    ScanSmem* sm = (ScanSmem*)smraw;

    const int tid  = threadIdx.x;
    const int warp = tid >> 5;
    const int lane = tid & 31;
    const int b    = blockIdx.x >> 7;           // 128 blocks per batch
    const int i0   = (blockIdx.x & 127) * SCH;
    const int chw  = (warp << 1) + (lane >> 4); // channel in block [0,16)
    const int i    = i0 + chw;
    const int sub  = lane & 15;
    const int s0   = sub << 2;

    float A2[4];
#pragma unroll
    for (int j = 0; j < 4; j++)
        A2[j] = -__expf(A_log[s0 + j]) * 1.4426950408889634f;  // A * log2(e)

    if (tid < 16) {
        sm->Dsm[tid] = D_param[i0 + tid];
        sm->CB[tid]  = conv_b[i0 + tid];
    } else if (tid < 80) {
        int t2 = tid - 16;
        sm->CW[t2 >> 2][t2 & 3] = conv_w[(i0 + (t2 >> 2)) * DCONV + (t2 & 3)];
    }

    float h0 = 0.f, h1 = 0.f, h2 = 0.f, h3 = 0.f;

    auto fill = [&](int buf, int c) {
        const int t0 = c * SW;
        const float* basebc = proj + ((size_t)(b * TLEN + t0)) * DPROJ + 2 * DINNER;
#pragma unroll
        for (int it = 0; it < 4; it++) {
            int idx = it * 256 + tid;
            int r = idx >> 5, cc = idx & 31;
            cpa16(smem_to_u32(&sm->BC[buf][r][cc * 4]), basebc + (size_t)r * DPROJ + cc * 4);
        }
        if (tid < 128) {
            int r = tid >> 2, cc = (tid & 3) * 4;
            size_t rowi = (size_t)(b * TLEN + t0 + r);
            cpa16(smem_to_u32(&sm->D[buf][r][cc]), delta + rowi * DINNER + i0 + cc);
        } else {
            int t2 = tid - 128;
            int r = t2 >> 2, cc = (t2 & 3) * 4;
            size_t rowi = (size_t)(b * TLEN + t0 + r);
            cpa16(smem_to_u32(&sm->Z[buf][r][cc]), proj + rowi * DPROJ + DINNER + i0 + cc);
        }
        if (tid < 144) {
            int rr = tid >> 2, cc = (tid & 3) * 4;
            int gt = t0 - 3 + rr;
            if (gt >= 0 && gt < TLEN) {
                cpa16(smem_to_u32(&sm->XI[buf][rr][cc]),
                      proj + ((size_t)(b * TLEN + gt)) * DPROJ + i0 + cc);
            } else {
                *(float4*)&sm->XI[buf][rr][cc] = make_float4(0.f, 0.f, 0.f, 0.f);
            }
        }
    };

    fill(0, 0); cpa_commit();
    fill(1, 1); cpa_commit();

    for (int c = 0; c < SNCH; c++) {
        const int buf = c & 1;
        cpa_wait<1>();
        __syncthreads();

        // conv + bias + silu + DU2 pack: 2 values/thread
        {
            int idx = tid * 2;
            int t = idx >> 4, ch = idx & 15;
#pragma unroll
            for (int v = 0; v < 2; v++) {
                float a = sm->CB[ch + v];
#pragma unroll
                for (int k = 0; k < DCONV; k++)
                    a = fmaf(sm->XI[buf][t + k][ch + v], sm->CW[ch + v][k], a);
                float xcv = a * sigmoidf_(a);
                sm->XC[buf][t][ch + v] = xcv;
                float dv = sm->D[buf][t][ch + v];
                sm->DU2[buf][t][ch + v] = make_float2(dv, dv * xcv);
            }
        }
        __syncthreads();

#pragma unroll 8
        for (int t = 0; t < SW; t++) {
            float2 dd = sm->DU2[buf][t][chw];   // (delta, delta*xc)
            float4 Bv = *(const float4*)&sm->BC[buf][t][s0];
            float4 Cv = *(const float4*)&sm->BC[buf][t][64 + s0];

            h0 = fmaf(ex2f(A2[0] * dd.x), h0, dd.y * Bv.x);
            h1 = fmaf(ex2f(A2[1] * dd.x), h1, dd.y * Bv.y);
            h2 = fmaf(ex2f(A2[2] * dd.x), h2, dd.y * Bv.z);
            h3 = fmaf(ex2f(A2[3] * dd.x), h3, dd.y * Bv.w);

            sm->P[t][chw][sub] =
                fmaf(h0, Cv.x, fmaf(h1, Cv.y, fmaf(h2, Cv.z, h3 * Cv.w)));
        }
        __syncthreads();

        {
            const int t0 = c * SW;
            int t = tid >> 3, chp = (tid & 7) * 2;
            float s0v = 0.f, s1v = 0.f;
            const float4* p0 = (const float4*)&sm->P[t][chp][0];
            const float4* p1 = (const float4*)&sm->P[t][chp + 1][0];
#pragma unroll
            for (int j = 0; j < 4; j++) {
                float4 v0 = p0[j], v1 = p1[j];
                s0v += (v0.x + v0.y) + (v0.z + v0.w);
                s1v += (v1.x + v1.y) + (v1.z + v1.w);
            }
            s0v = fmaf(sm->Dsm[chp],     sm->XC[buf][t][chp],     s0v);
            s1v = fmaf(sm->Dsm[chp + 1], sm->XC[buf][t][chp + 1], s1v);
            float z0 = sm->Z[buf][t][chp], z1 = sm->Z[buf][t][chp + 1];
            s0v *= z0 * sigmoidf_(z0);
            s1v *= z1 * sigmoidf_(z1);
            *(__half2*)(yh + ((size_t)(b * TLEN + t0 + t)) * DINNER + i0 + chp) =
                __floats2half2_rn(s0v, s1v);
        }
        __syncthreads();

        if (c + 2 < SNCH) fill(buf, c + 2);
        cpa_commit();
    }

    *(float4*)(hT + ((size_t)(b * DINNER + i)) * DSTATE + s0) = make_float4(h0, h1, h2, h3);
}

// ---------------- launch ----------------
extern "C" void kernel_launch(void* const* d_in, const int* in_sizes, int n_in,
                              void* d_out, int out_size)
{
    const float* x       = (const float*)d_in[0];   // [2,2048,1024]
    const float* in_proj = (const float*)d_in[1];   // [4288,1024]
    const float* conv_w  = (const float*)d_in[2];   // [2048,1,4]
    const float* conv_b  = (const float*)d_in[3];   // [2048]
    const float* A_log   = (const float*)d_in[4];   // [64]
    const float* D_param = (const float*)d_in[5];   // [2048]
    const float* dt_w    = (const float*)d_in[6];   // [2048,64]
    const float* dt_b    = (const float*)d_in[7];   // [2048]
    const float* out_w   = (const float*)d_in[8];   // [1024,2048]
    float* out = (float*)d_out;                     // out (4194304) then hT (262144)

    float *pproj, *pdelta;
    cudaGetSymbolAddress((void**)&pproj,  g_proj);
    cudaGetSymbolAddress((void**)&pdelta, g_delta);

    __half *xh, *w1h, *w2h, *yh;
    cudaGetSymbolAddress((void**)&xh,  g_xh);
    cudaGetSymbolAddress((void**)&w1h, g_w1h);
    cudaGetSymbolAddress((void**)&w2h, g_w2h);
    cudaGetSymbolAddress((void**)&yh,  g_yh);

    cudaFuncSetAttribute(gemm_mma_fp16,
                         cudaFuncAttributeMaxDynamicSharedMemorySize, SMEMB);
    cudaFuncSetAttribute(scan_kernel4,
                         cudaFuncAttributeMaxDynamicSharedMemorySize, (int)sizeof(ScanSmem));

    // convert inputs to fp16
    {
        int n4 = (MROWS * DMODEL) / 4;
        cvt_fp16_kernel<<<(n4 + 255) / 256, 256>>>(x, xh, n4);
        n4 = (DPROJ * DMODEL) / 4;
        cvt_fp16_kernel<<<(n4 + 255) / 256, 256>>>(in_proj, w1h, n4);
        n4 = (DMODEL * DINNER) / 4;
        cvt_fp16_kernel<<<(n4 + 255) / 256, 256>>>(out_w, w2h, n4);
    }

    // 1) proj = x @ in_proj_w^T   [4096 x 4288]  (HMMA fp16, BK=64)
    gemm_mma_fp16<<<dim3((DPROJ + 127) / 128, MROWS / 128), 256, SMEMB>>>(
        xh, w1h, pproj, MROWS, DPROJ, DMODEL);

    // 2) delta = softplus(delta_raw @ dt_proj_w^T + dt_proj_b)  [4096 x 2048] K=64 (SIMT)
    gemm_nt<1><<<dim3(DINNER / 128, MROWS / 128), 256>>>(
        pproj + 2 * DINNER + 2 * DSTATE, DPROJ, dt_w, DTRANK, pdelta, DINNER,
        MROWS, DINNER, DTRANK, dt_b);

    // 3) selective scan v4b (conv+silu fused, packed DU2); writes yh fp16 + hT tail
    scan_kernel4<<<256, 256, sizeof(ScanSmem)>>>(pproj, pdelta, A_log, D_param,
                                                 conv_w, conv_b,
                                                 yh, out + (size_t)MROWS * DMODEL);

    // 4) out = y @ out_proj_w^T   [4096 x 1024]  (HMMA fp16, BK=64)
    gemm_mma_fp16<<<dim3(DMODEL / 128, MROWS / 128), 256, SMEMB>>>(
        yh, w2h, out, MROWS, DMODEL, DINNER);
}